// round 17
// baseline (speedup 1.0000x reference)
#include <cuda_runtime.h>
#include <cuda_bf16.h>

#define NV 100000
#define NE 200000
#define NF 100000
#define N_EV 400000
#define N_FE 800000
#define N_FF 800000
#define WD 128
#define NDST_TOT (NE + NF + NF)
#define NEDGE_TOT (N_EV + N_FE + N_FF)

__device__ __align__(16) float g_xv[NV * WD];
__device__ __align__(16) float g_xe[NE * WD];
// bf16 hi/lo images: row stride 1024 B = [hi bf16[256] | lo bf16[256]]
__device__ __align__(16) unsigned char g_imgE[(size_t)NE * 1024];
__device__ __align__(16) unsigned char g_imgF[(size_t)NF * 1024];
__device__ __align__(16) unsigned char g_wimg[4 * 131072];  // per W: [hi 64KB | lo 64KB], [k][n]
__device__ int g_cnt[NDST_TOT];
__device__ int g_ptr[NDST_TOT];
__device__ int g_cur[NDST_TOT];
__device__ int g_bsum[256];
__device__ int g_csr[NEDGE_TOT];
__device__ unsigned g_barcnt;
__device__ volatile unsigned g_bargen;

typedef unsigned long long u64;

__device__ __forceinline__ u64 pk2(float lo, float hi) {
    u64 r; asm("mov.b64 %0, {%1,%2};" : "=l"(r) : "f"(lo), "f"(hi)); return r;
}
__device__ __forceinline__ float2 upk2(u64 v) {
    float2 r; asm("mov.b64 {%0,%1}, %2;" : "=f"(r.x), "=f"(r.y) : "l"(v)); return r;
}
__device__ __forceinline__ u64 ffma2(u64 a, u64 b, u64 c) {
    u64 d; asm("fma.rn.f32x2 %0, %1, %2, %3;" : "=l"(d) : "l"(a), "l"(b), "l"(c)); return d;
}
__device__ __forceinline__ void cp16(unsigned dst, const void* src, int srcsz) {
    asm volatile("cp.async.cg.shared.global [%0], [%1], 16, %2;"
                 :: "r"(dst), "l"(src), "r"(srcsz));
}
#define CP_COMMIT() asm volatile("cp.async.commit_group;")
#define CP_WAIT1()  asm volatile("cp.async.wait_group 1;")
#define CP_WAIT0()  asm volatile("cp.async.wait_group 0;")

__device__ __forceinline__ unsigned split2(float a, float b, float& la, float& lb) {
    __nv_bfloat162 h = __floats2bfloat162_rn(a, b);
    float2 hf = __bfloat1622float2(h);
    la = a - hf.x; lb = b - hf.y;
    return *reinterpret_cast<unsigned*>(&h);
}
__device__ __forceinline__ unsigned pack2(float a, float b) {
    __nv_bfloat162 h = __floats2bfloat162_rn(a, b);
    return *reinterpret_cast<unsigned*>(&h);
}

#define LDSM4(r, a) \
    asm volatile("ldmatrix.sync.aligned.m8n8.x4.shared.b16 {%0,%1,%2,%3}, [%4];" \
        : "=r"((r)[0]), "=r"((r)[1]), "=r"((r)[2]), "=r"((r)[3]) : "r"(a))
#define LDSM4T(r, a) \
    asm volatile("ldmatrix.sync.aligned.m8n8.x4.trans.shared.b16 {%0,%1,%2,%3}, [%4];" \
        : "=r"((r)[0]), "=r"((r)[1]), "=r"((r)[2]), "=r"((r)[3]) : "r"(a))
#define MMA16816(d, a, b0, b1) \
    asm volatile("mma.sync.aligned.m16n8k16.row.col.f32.bf16.bf16.f32 " \
        "{%0,%1,%2,%3}, {%4,%5,%6,%7}, {%8,%9}, {%0,%1,%2,%3};" \
        : "+f"((d)[0]), "+f"((d)[1]), "+f"((d)[2]), "+f"((d)[3]) \
        : "r"((a)[0]), "r"((a)[1]), "r"((a)[2]), "r"((a)[3]), "r"(b0), "r"(b1))

// ---------------- software global barrier ----------------
__device__ __forceinline__ void gbar() {
    __syncthreads();
    if (threadIdx.x == 0) {
        unsigned gen = g_bargen;
        __threadfence();
        if (atomicAdd(&g_barcnt, 1) == gridDim.x - 1) {
            g_barcnt = 0; __threadfence(); g_bargen = gen + 1;
        } else { while (g_bargen == gen) __nanosleep(64); }
        __threadfence();
    }
    __syncthreads();
}

__device__ __forceinline__ int block_scan_incl(int v, int* tot, int* swarp) {
    int lane = threadIdx.x & 31, wid = threadIdx.x >> 5;
    int s = v;
#pragma unroll
    for (int o = 1; o < 32; o <<= 1) { int t = __shfl_up_sync(~0u, s, o); if (lane >= o) s += t; }
    if (lane == 31) swarp[wid] = s;
    __syncthreads();
    if (wid == 0) {
        int w = swarp[lane];
#pragma unroll
        for (int o = 1; o < 32; o <<= 1) { int t = __shfl_up_sync(~0u, w, o); if (lane >= o) w += t; }
        swarp[lane] = w;
    }
    __syncthreads();
    int add = (wid > 0) ? swarp[wid - 1] : 0;
    *tot = swarp[31];
    int r = s + add;
    __syncthreads();
    return r;
}

// ---------------- build all 3 CSRs in ONE kernel ----------------
__global__ void __launch_bounds__(1024)
build_csr_all(const int* __restrict__ etv_v, const int* __restrict__ etv_e,
              const int* __restrict__ fte_e, const int* __restrict__ fte_f,
              const int* __restrict__ ftf_src, const int* __restrict__ ftf_dst)
{
    __shared__ int swarp[32];
    int gtid = blockIdx.x * 1024 + threadIdx.x, gs = gridDim.x * 1024;
    for (int i = gtid; i < NDST_TOT; i += gs) g_cnt[i] = 0;
    gbar();
    for (int e = gtid; e < N_EV; e += gs) atomicAdd(&g_cnt[__ldg(etv_e + e)], 1);
    for (int e = gtid; e < N_FE; e += gs) atomicAdd(&g_cnt[NE + __ldg(fte_f + e)], 1);
    for (int e = gtid; e < N_FF; e += gs) atomicAdd(&g_cnt[NE + NF + __ldg(ftf_dst + e)], 1);
    gbar();
    const int CHUNK = (NDST_TOT + gridDim.x - 1) / gridDim.x;
    int base = blockIdx.x * CHUNK, lim = min(base + CHUNK, NDST_TOT), carry = 0;
    for (int t = base; t < base + CHUNK; t += 1024) {
        int i = t + threadIdx.x;
        int v = (i < lim) ? g_cnt[i] : 0;
        int tot; int incl = block_scan_incl(v, &tot, swarp);
        if (i < lim) g_ptr[i] = carry + incl - v;
        carry += tot;
    }
    if (threadIdx.x == 0) g_bsum[blockIdx.x] = carry;
    gbar();
    if (blockIdx.x == 0) {
        int v = ((int)threadIdx.x < (int)gridDim.x) ? g_bsum[threadIdx.x] : 0;
        int tot; int incl = block_scan_incl(v, &tot, swarp);
        if ((int)threadIdx.x < (int)gridDim.x) g_bsum[threadIdx.x] = incl - v;
    }
    gbar();
    {
        int off = g_bsum[blockIdx.x];
        for (int i = base + threadIdx.x; i < lim; i += 1024) {
            int p = g_ptr[i] + off; g_ptr[i] = p; g_cur[i] = p;
        }
    }
    gbar();
    for (int e = gtid; e < N_EV; e += gs) {
        int d = __ldg(etv_e + e);
        g_csr[atomicAdd(&g_cur[d], 1)] = __ldg(etv_v + e);
    }
    for (int e = gtid; e < N_FE; e += gs) {
        int d = NE + __ldg(fte_f + e);
        g_csr[atomicAdd(&g_cur[d], 1)] = __ldg(fte_e + e);
    }
    for (int e = gtid; e < N_FF; e += gs) {
        int d = NE + NF + __ldg(ftf_dst + e);
        g_csr[atomicAdd(&g_cur[d], 1)] = __ldg(ftf_src + e);
    }
}

// ---------------- W split: 4 weights -> bf16 hi/lo images [k][n] linear ----------------
__global__ void wsplit_kernel(const float* __restrict__ W0, const float* __restrict__ W1,
                              const float* __restrict__ W2, const float* __restrict__ W3)
{
    const float* Wm = blockIdx.x == 0 ? W0 : blockIdx.x == 1 ? W1 : blockIdx.x == 2 ? W2 : W3;
    unsigned char* base = g_wimg + (size_t)blockIdx.x * 131072;
    for (int i = threadIdx.x; i < 256 * 64; i += 256) {
        int k = i >> 6, n2 = (i & 63) * 2;
        float v0 = __ldg(Wm + k * WD + n2), v1 = __ldg(Wm + k * WD + n2 + 1);
        float l0, l1;
        unsigned hv = split2(v0, v1, l0, l1);
        unsigned lv = pack2(l0, l1);
        *(unsigned*)(base + k * 256 + n2 * 2) = hv;
        *(unsigned*)(base + 65536 + k * 256 + n2 * 2) = lv;
    }
}

// ---------------- embeddings: warp per 4 rows; optional split write to img cols 0-127 ----------------
template<int CIN>
__global__ void embed4_kernel(const float* __restrict__ in, const float* __restrict__ Wt,
                              const float* __restrict__ bias, float* __restrict__ out,
                              unsigned char* __restrict__ img, int n)
{
    __shared__ u64 sW2[CIN * 64];
    __shared__ u64 sB2[64];
    for (int i = threadIdx.x; i < CIN * 64; i += 256) sW2[i] = *(const u64*)(Wt + 2 * i);
    if (threadIdx.x < 64) sB2[threadIdx.x] = *(const u64*)(bias + 2 * threadIdx.x);
    __syncthreads();
    int w4 = (blockIdx.x * 8 + (threadIdx.x >> 5)) * 4;
    if (w4 >= n) return;
    int lane = threadIdx.x & 31;
    float x0 = 0.f, x1 = 0.f;
    {
        long long b = (long long)w4 * CIN;
        long long tot = (long long)n * CIN;
        if (lane < 4 * CIN && b + lane < tot) x0 = __ldg(in + b + lane);
        if (32 + lane < 4 * CIN && b + 32 + lane < tot) x1 = __ldg(in + b + 32 + lane);
    }
    u64 a[4][2];
#pragma unroll
    for (int r = 0; r < 4; r++) { a[r][0] = sB2[2 * lane]; a[r][1] = sB2[2 * lane + 1]; }
#pragma unroll
    for (int k = 0; k < CIN; k++) {
        u64 w0 = sW2[k * 64 + 2 * lane], w1 = sW2[k * 64 + 2 * lane + 1];
#pragma unroll
        for (int r = 0; r < 4; r++) {
            int p = r * CIN + k;
            float xk = (p < 32) ? __shfl_sync(~0u, x0, p) : __shfl_sync(~0u, x1, p - 32);
            u64 h2 = pk2(xk, xk);
            a[r][0] = ffma2(h2, w0, a[r][0]);
            a[r][1] = ffma2(h2, w1, a[r][1]);
        }
    }
#pragma unroll
    for (int r = 0; r < 4; r++) {
        int row = w4 + r;
        if (row < n) {
            float2 v0 = upk2(a[r][0]), v1 = upk2(a[r][1]);
            float4 o;
            o.x = v0.x > 0.f ? v0.x : 0.01f * v0.x;
            o.y = v0.y > 0.f ? v0.y : 0.01f * v0.y;
            o.z = v1.x > 0.f ? v1.x : 0.01f * v1.x;
            o.w = v1.y > 0.f ? v1.y : 0.01f * v1.y;
            *(float4*)(out + (size_t)row * WD + lane * 4) = o;
            if (img) {
                float l0, l1, l2, l3;
                uint2 hv, lv;
                hv.x = split2(o.x, o.y, l0, l1); hv.y = split2(o.z, o.w, l2, l3);
                lv.x = pack2(l0, l1); lv.y = pack2(l2, l3);
                unsigned char* p = img + (size_t)row * 1024 + lane * 8;
                *(uint2*)p = hv;
                *(uint2*)(p + 512) = lv;
            }
        }
    }
}

// ---------------- segmin -> split write to img cols 128-255 ----------------
__global__ void segmin_kernel(const float* __restrict__ xsrc, const float* __restrict__ xdst,
                              const int* __restrict__ ptr, const int* __restrict__ cnt,
                              const int* __restrict__ csr, unsigned char* __restrict__ img, int ndst)
{
    int w = (blockIdx.x * blockDim.x + threadIdx.x) >> 5;
    if (w >= ndst) return;
    int lane = threadIdx.x & 31;
    int deg = __ldg(cnt + w), base = __ldg(ptr + w);
    const float inf = __int_as_float(0x7f800000);
    float4 mn = make_float4(inf, inf, inf, inf);
    int i = 0;
    for (; i + 4 <= deg; i += 4) {
        int s0 = __ldg(csr + base + i), s1 = __ldg(csr + base + i + 1);
        int s2 = __ldg(csr + base + i + 2), s3 = __ldg(csr + base + i + 3);
        float4 v0 = __ldg((const float4*)(xsrc + (size_t)s0 * WD) + lane);
        float4 v1 = __ldg((const float4*)(xsrc + (size_t)s1 * WD) + lane);
        float4 v2 = __ldg((const float4*)(xsrc + (size_t)s2 * WD) + lane);
        float4 v3 = __ldg((const float4*)(xsrc + (size_t)s3 * WD) + lane);
        mn.x = fminf(mn.x, fminf(fminf(v0.x, v1.x), fminf(v2.x, v3.x)));
        mn.y = fminf(mn.y, fminf(fminf(v0.y, v1.y), fminf(v2.y, v3.y)));
        mn.z = fminf(mn.z, fminf(fminf(v0.z, v1.z), fminf(v2.z, v3.z)));
        mn.w = fminf(mn.w, fminf(fminf(v0.w, v1.w), fminf(v2.w, v3.w)));
    }
    for (; i < deg; i++) {
        int s = __ldg(csr + base + i);
        float4 v = __ldg((const float4*)(xsrc + (size_t)s * WD) + lane);
        mn.x = fminf(mn.x, v.x); mn.y = fminf(mn.y, v.y);
        mn.z = fminf(mn.z, v.z); mn.w = fminf(mn.w, v.w);
    }
    float4 o = make_float4(0.f, 0.f, 0.f, 0.f);
    if (deg > 0) {
        float4 a = __ldg((const float4*)(xdst + (size_t)w * WD) + lane);
        o = make_float4(a.x - mn.x, a.y - mn.y, a.z - mn.z, a.w - mn.w);
    }
    float l0, l1, l2, l3;
    uint2 hv, lv;
    hv.x = split2(o.x, o.y, l0, l1); hv.y = split2(o.z, o.w, l2, l3);
    lv.x = pack2(l0, l1); lv.y = pack2(l2, l3);
    unsigned char* p = img + (size_t)w * 1024 + 256 + lane * 8;
    *(uint2*)p = hv;
    *(uint2*)(p + 512) = lv;
}

// ---------------- persistent conv GEMM via mma.sync bf16 3-term split ----------------
// out = xdst + lrelu([xdst|maxes] @ Wm + bm); D = AhiWhi + AhiWlo + AloWhi (fp32 acc).
// Warp tile 32 rows x 64 cols (rw = w&3, cw = w>>2): B-fragment LDSM traffic halved.
#define CONV_THREADS 256
#define TILE_R 128
#define SW_LO 65536
#define SBIAS_B 131072
#define SHB 131584
#define CONV_SMEM 197120

__device__ __forceinline__ void conv_issue_chunk_b(
    unsigned sb, const unsigned char* img, int tile, int c, int n, int tid)
{
    int row0 = tile * TILE_R;
#pragma unroll
    for (int t = 0; t < 8; t++) {
        int idx = tid + t * 256;
        int row = idx >> 4, q = idx & 15;
        int u = q & 7, half = q >> 3;            // 0 = hi, 1 = lo
        int gr = row0 + row;
        int sz = (gr < n) ? 16 : 0;
        const unsigned char* src = img + (size_t)gr * 1024 + half * 512 + c * 128 + u * 16;
        unsigned dst = sb + SHB + (c & 1) * 32768 + half * 16384 + row * 128 + ((u ^ (row & 7)) * 16);
        cp16(dst, src, sz);
    }
}

__global__ void __launch_bounds__(CONV_THREADS, 1)
conv_mma(const unsigned char* __restrict__ img, const unsigned char* __restrict__ wimg,
         const float* __restrict__ bm, const float* __restrict__ xdst,
         float* __restrict__ out, unsigned char* __restrict__ nextimg,
         int n, int ntiles)
{
    extern __shared__ float smem[];
    unsigned sb = (unsigned)__cvta_generic_to_shared(smem);
    float* sBf = (float*)((char*)smem + SBIAS_B);

    int tid = threadIdx.x;
    int bid = blockIdx.x, stride = gridDim.x;
    if (bid >= ntiles) return;

    // resident W hi/lo (swizzled dst) + first two h chunks
    {
#pragma unroll
        for (int t = 0; t < 32; t++) {
            int idx = tid + t * 256;                 // 8192 units
            int half = idx >> 12;
            int k = (idx & 4095) >> 4, u = idx & 15;
            int su = ((u ^ k) & 7) | (u & 8);
            cp16(sb + half * SW_LO + k * 256 + su * 16,
                 wimg + half * SW_LO + k * 256 + u * 16, 16);
        }
        conv_issue_chunk_b(sb, img, bid, 0, n, tid);
        CP_COMMIT();
        conv_issue_chunk_b(sb, img, bid, 1, n, tid);
        CP_COMMIT();
    }
    if (tid < WD) sBf[tid] = bm[tid];

    int lane = tid & 31, w = tid >> 5;
    int rw = w & 3, cw = w >> 2;                     // 4 row-groups x 2 col-groups
    int mi = lane >> 3, li = lane & 7;
    // A lane geometry: two 16-row sets at rows 32*rw + 16*set
    int a_rbase = 32 * rw + li + (mi & 1) * 8;       // set 0 row
    int a_rx = a_rbase & 7;                          // same for set 1 (+16 keeps &7)
    int a_uoff = mi >> 1;
    // B lane geometry
    int b_krl = li + (mi & 1) * 8;
    int b_uoff = mi >> 1;
    int b_x = li;

    float acc[2][8][4];

#pragma unroll 1
    for (int t = bid; t < ntiles; t += stride) {
#pragma unroll 1
        for (int c = 0; c < 4; c++) {
            CP_WAIT1();
            __syncthreads();
            if (c == 0) {
#pragma unroll
                for (int st = 0; st < 2; st++)
#pragma unroll
                    for (int nt = 0; nt < 8; nt++)
#pragma unroll
                        for (int q = 0; q < 4; q++) acc[st][nt][q] = 0.f;
            }
            unsigned hb0 = sb + SHB + (c & 1) * 32768;
#pragma unroll
            for (int s = 0; s < 4; s++) {
                int ua = (2 * s + a_uoff) ^ a_rx;
                unsigned ah[2][4], al[2][4];
#pragma unroll
                for (int st = 0; st < 2; st++) {
                    unsigned hrow = hb0 + (a_rbase + 16 * st) * 128;
                    LDSM4(ah[st], hrow + ua * 16);
                    LDSM4(al[st], hrow + 16384 + ua * 16);
                }
                unsigned wrow = sb + (unsigned)(c * 64 + s * 16 + b_krl) * 256;
#pragma unroll
                for (int np = 0; np < 4; np++) {
                    int u = 2 * (4 * cw + np) + b_uoff;
                    int su = ((u ^ b_x) & 7) | (u & 8);
                    unsigned bh[4], bl[4];
                    LDSM4T(bh, wrow + su * 16);
                    LDSM4T(bl, wrow + SW_LO + su * 16);
#pragma unroll
                    for (int st = 0; st < 2; st++) {
                        MMA16816(acc[st][2 * np], ah[st], bh[0], bh[1]);
                        MMA16816(acc[st][2 * np], ah[st], bl[0], bl[1]);
                        MMA16816(acc[st][2 * np], al[st], bh[0], bh[1]);
                        MMA16816(acc[st][2 * np + 1], ah[st], bh[2], bh[3]);
                        MMA16816(acc[st][2 * np + 1], ah[st], bl[2], bl[3]);
                        MMA16816(acc[st][2 * np + 1], al[st], bh[2], bh[3]);
                    }
                }
            }
            __syncthreads();
            int tn = (c < 2) ? t : t + stride;
            int cn = (c < 2) ? c + 2 : c - 2;
            if (tn < ntiles) conv_issue_chunk_b(sb, img, tn, cn, n, tid);
            CP_COMMIT();
        }
        // epilogue: bias + lrelu + residual (+ optional split to nextimg)
        int g = lane >> 2, tq = lane & 3;
        int row0 = t * TILE_R;
#pragma unroll
        for (int st = 0; st < 2; st++) {
            int r_lo = row0 + 32 * rw + 16 * st + g;
#pragma unroll
            for (int nt = 0; nt < 8; nt++) {
                int col = 64 * cw + 8 * nt + 2 * tq;
                float b0 = sBf[col], b1 = sBf[col + 1];
#pragma unroll
                for (int h = 0; h < 2; h++) {
                    int row = r_lo + 8 * h;
                    if (row < n) {
                        float v0 = acc[st][nt][2 * h] + b0;
                        float v1 = acc[st][nt][2 * h + 1] + b1;
                        v0 = v0 > 0.f ? v0 : 0.01f * v0;
                        v1 = v1 > 0.f ? v1 : 0.01f * v1;
                        float2 x = __ldg((const float2*)(xdst + (size_t)row * WD + col));
                        float2 res; res.x = x.x + v0; res.y = x.y + v1;
                        *(float2*)(out + (size_t)row * WD + col) = res;
                        if (nextimg) {
                            float l0, l1;
                            unsigned hv = split2(res.x, res.y, l0, l1);
                            unsigned lv = pack2(l0, l1);
                            unsigned char* p = nextimg + (size_t)row * 1024 + col * 2;
                            *(unsigned*)p = hv;
                            *(unsigned*)(p + 512) = lv;
                        }
                    }
                }
            }
        }
    }
}

// ---------------- launch ----------------
extern "C" void kernel_launch(void* const* d_in, const int* in_sizes, int n_in,
                              void* d_out, int out_size)
{
    const float* vertices = (const float*)d_in[0];
    const float* edges    = (const float*)d_in[1];
    const float* faces    = (const float*)d_in[2];
    const int* etv_v   = (const int*)d_in[3];
    const int* etv_e   = (const int*)d_in[4];
    const int* fte_e   = (const int*)d_in[5];
    const int* fte_f   = (const int*)d_in[6];
    const int* ftf_src = (const int*)d_in[7];
    const int* ftf_dst = (const int*)d_in[8];
    const float* Wv   = (const float*)d_in[9];
    const float* bv   = (const float*)d_in[10];
    const float* We   = (const float*)d_in[11];
    const float* be   = (const float*)d_in[12];
    const float* Wf   = (const float*)d_in[13];
    const float* bf   = (const float*)d_in[14];
    const float* Wv2e = (const float*)d_in[15];
    const float* bv2e = (const float*)d_in[16];
    const float* We2f = (const float*)d_in[17];
    const float* be2f = (const float*)d_in[18];
    const float* Wm0  = (const float*)d_in[19];
    const float* bm0  = (const float*)d_in[20];
    const float* Wm1  = (const float*)d_in[21];
    const float* bm1  = (const float*)d_in[22];

    float *xv, *xe;
    int *cnt, *ptr, *csr;
    unsigned char *imgE, *imgF, *wimg;
    cudaGetSymbolAddress((void**)&xv, g_xv);
    cudaGetSymbolAddress((void**)&xe, g_xe);
    cudaGetSymbolAddress((void**)&cnt, g_cnt);
    cudaGetSymbolAddress((void**)&ptr, g_ptr);
    cudaGetSymbolAddress((void**)&csr, g_csr);
    cudaGetSymbolAddress((void**)&imgE, g_imgE);
    cudaGetSymbolAddress((void**)&imgF, g_imgF);
    cudaGetSymbolAddress((void**)&wimg, g_wimg);
    float* xf = (float*)d_out;

    cudaFuncSetAttribute(conv_mma, cudaFuncAttributeMaxDynamicSharedMemorySize, CONV_SMEM);

    const int NT_E = (NE + TILE_R - 1) / TILE_R;
    const int NT_F = (NF + TILE_R - 1) / TILE_R;

    // order chosen so ncu's sampled launch (index 5) is conv_mma V2E
    build_csr_all<<<148, 1024>>>(etv_v, etv_e, fte_e, fte_f, ftf_src, ftf_dst);       // 0
    embed4_kernel<3><<<(NV + 31) / 32, 256>>>(vertices, Wv, bv, xv, (unsigned char*)0, NV);  // 1
    embed4_kernel<12><<<(NE + 31) / 32, 256>>>(edges, We, be, xe, imgE, NE);          // 2
    wsplit_kernel<<<4, 256>>>(Wv2e, We2f, Wm0, Wm1);                                  // 3

    // V2E
    segmin_kernel<<<(NE + 7) / 8, 256>>>(xv, xe, ptr, cnt, csr, imgE, NE);            // 4
    conv_mma<<<148, CONV_THREADS, CONV_SMEM>>>(imgE, wimg, bv2e, xe, xe,
                                               (unsigned char*)0, NE, NT_E);          // 5 (profiled)

    embed4_kernel<14><<<(NF + 31) / 32, 256>>>(faces, Wf, bf, xf, imgF, NF);          // 6

    // E2F
    segmin_kernel<<<(NF + 7) / 8, 256>>>(xe, xf, ptr + NE, cnt + NE, csr, imgF, NF);
    conv_mma<<<148, CONV_THREADS, CONV_SMEM>>>(imgF, wimg + 131072, be2f, xf, xf,
                                               imgF, NF, NT_F);

    // FF layer 0
    segmin_kernel<<<(NF + 7) / 8, 256>>>(xf, xf, ptr + NE + NF, cnt + NE + NF, csr, imgF, NF);
    conv_mma<<<148, CONV_THREADS, CONV_SMEM>>>(imgF, wimg + 2 * 131072, bm0, xf, xf,
                                               imgF, NF, NT_F);

    // FF layer 1
    segmin_kernel<<<(NF + 7) / 8, 256>>>(xf, xf, ptr + NE + NF, cnt + NE + NF, csr, imgF, NF);
    conv_mma<<<148, CONV_THREADS, CONV_SMEM>>>(imgF, wimg + 3 * 131072, bm1, xf, xf,
                                               (unsigned char*)0, NF, NT_F);
}